// round 17
// baseline (speedup 1.0000x reference)
#include <cuda_runtime.h>
#include <math_constants.h>

// ---------------------------------------------------------------------------
// APPM: 13-ratio sliding-window avg pooling (smem SAT) + 3-group greedy NMS
// (picks 2/3/2, IoU 0.25), batch 256.
//
// Round-17 = round-16 + NMS scans rewritten as rolling y-chains: each thread
// walks tiles (xi fixed, yq += rw), carrying the left corner blocks TL/BL in
// registers so each tile costs 2 LDS.128 (not 4), and all x-side suppression
// constants hoist out of the inner loop. Chains are flat-enumerated across
// the group's ratios (compile-time dispatch). Scoring pass, SAT prefix scans,
// reductions unchanged from R16. Suppression stays division-free:
// 5*inter > areaW + selarea (exact small ints in fp32 == IoU > 0.25).
//
// Output layout (float32):
//   [0,1792)               proposalN_indices  (256 x 7) as float
//   [1792,3584)            proposalN_windows_scores (256 x 7)
//   [3584, 3584+256*96981) window_scores (256 x 96981)
// ---------------------------------------------------------------------------

#define FEAT   112
#define SATN   113
#define SATP   116            // padded SAT row stride (multiple of 4)
#define NRAT   13
#define NBATCH 256
#define NTOTAL 96981
#define PROPN  7
#define NTH    1024
#define NYS    1160           // per-slot hy-table floats (padded nc summed)
#define NEGINF (-CUDART_INF_F)

__host__ __device__ constexpr int cRH(int r) {
    constexpr int a[NRAT] = {16,12,20,24,20,28,32,24,40,28,40,28,36};
    return a[r];
}
__host__ __device__ constexpr int cRW(int r) {
    constexpr int a[NRAT] = {16,20,12,24,28,20,32,40,24,40,28,36,28};
    return a[r];
}
__host__ __device__ constexpr int cBASE(int r) {
    constexpr int a[NRAT+1] = {0,9409,18802,28195,36116,44021,51926,58487,
                               64984,71481,77686,83891,90436,96981};
    return a[r];
}
// prefix sums of padded-to-4 nc (nc = 113-RW)
__host__ __device__ constexpr int cYQ(int r) {
    constexpr int a[NRAT] = {0,100,196,300,392,480,576,660,736,828,904,992,1072};
    return a[r];
}
// cumulative chain counts: chains_r = (113-RH) * (RW/4)
__host__ __device__ constexpr int cCC(int r) {
    constexpr int a[NRAT+1] = {0,388,893,1172,1706,2357,2782,3430,4320,4758,
                               5608,6119,6884,7423};
    return a[r];
}

// dynamic smem (floats): SAT[113*116] | HYS[2*NYS]
#define SMEM_FLOATS (SATN*SATP + 2*NYS)

// warp-level pairwise merge (max score, min idx on tie)
__device__ __forceinline__ void wmerge(float& b, int& bi) {
    #pragma unroll
    for (int o = 16; o > 0; o >>= 1) {
        float os = __shfl_down_sync(0xffffffffu, b, o);
        int   oi = __shfl_down_sync(0xffffffffu, bi, o);
        if (os > b || (os == b && oi < bi)) { b = os; bi = oi; }
    }
}

// decode a winning window index into its box + area (lane0 only)
__device__ __forceinline__ void decode_box(int bidx, float* box, float* sa) {
    int rh = cRH(0), rw = cRW(0), bb = 0;
    #pragma unroll
    for (int r = 1; r < NRAT; r++)
        if (bidx >= cBASE(r)) { rh = cRH(r); rw = cRW(r); bb = cBASE(r); }
    int off = bidx - bb;
    int nc = SATN - rw;
    int xi = off / nc, yi = off - xi * nc;
    float x0u = (float)(4 * xi - 1), y0u = (float)(4 * yi - 1);
    float cx0 = fmaxf(x0u, 0.0f), cy0 = fmaxf(y0u, 0.0f);
    float cx1 = x0u + (float)(4 * rh);
    float cy1 = y0u + (float)(4 * rw);
    box[0] = cx0; box[1] = cy0; box[2] = cx1; box[3] = cy1;
    *sa = (cx1 - cx0 + 1.0f) * (cy1 - cy0 + 1.0f);
}

// fill hy table (full yi range incl. border yi=0; zero pad) for [R0,R1)
template<int R0, int R1>
__device__ __forceinline__ void fill_hys(
    int slot, int tid, float* HYS, const float* box)
{
    float by0 = box[1], by1 = box[3];
    #pragma unroll
    for (int r = R0; r < R1; r++) {
        const int rw = cRW(r);
        const int nc = SATN - rw;
        const int ncp = (nc + 3) & ~3;
        if (tid < ncp) {
            float h = 0.0f;
            if (tid < nc) {
                float y0u = (float)(4 * tid - 1);
                float y0 = fmaxf(y0u, 0.0f);
                float y1 = y0u + (float)(4 * rw);
                h = fmaxf(fminf(y1, by1) - fmaxf(y0, by0) + 1.0f, 0.0f);
            }
            HYS[slot * NYS + cYQ(r) + tid] = h;
        }
    }
}

// ---------------------------------------------------------------------------
// NMS scan, ratios [R0,R1), P priors (1 or 2), rolling y-chains.
// Each chain: fixed xi, tiles q = c, c+qstep, ... (qstep = rw/4). The left
// corner blocks TL/BL roll from the previous step's TR/BR -> 2 LDS.128/tile.
// x-side constants (w5a/rhs) computed once per chain. Scores use the EXACT
// scoring expression/order -> bit-identical. Suppress iff
// 5*inter > areaW + selarea. Strict '>' argmax (ascending visit order).
// ---------------------------------------------------------------------------
template<int R0, int R1, int P>
__device__ __forceinline__ void nms_scan(
    const float* __restrict__ S, const float* __restrict__ HYS,
    float bx0a, float bx1a, float saA,
    float bx0b, float bx1b, float saB,
    int tid, float& best, int& bidx)
{
    #pragma unroll 1
    for (int ci = cCC(R0) + tid; ci < cCC(R1); ci += NTH) {
        #pragma unroll
        for (int r = R0; r < R1; r++) {
            if (ci >= cCC(r) && ci < cCC(r + 1)) {
                const int rh = cRH(r), rw = cRW(r);
                const int nc = SATN - rw;
                const int nq = (nc + 3) >> 2;
                const int qstep = rw >> 2;
                const int base = cBASE(r);
                const int R_ = rh * SATP;
                const float inv = 1.0f / (float)(rh * rw);
                const float frh  = (float)(4 * rh), frw  = (float)(4 * rw);
                const float frh1 = frh + 1.0f,      frw1 = frw + 1.0f;

                int local = ci - cCC(r);
                int xi = local / qstep;         // qstep const -> mul/shift
                int c  = local - xi * qstep;

                // per-chain x-side constants
                float x0u = (float)(4 * xi - 1);
                float x0 = fmaxf(x0u, 0.0f), x1 = x0u + frh;
                float ax = (xi == 0) ? frh : frh1;
                float w5a = 5.0f * fmaxf(fminf(x1, bx1a) - fmaxf(x0, bx0a) + 1.0f, 0.0f);
                float rhsa  = fmaf(ax, frw1, saA);
                float rhsa0 = fmaf(ax, frw,  saA);    // yi == 0 (ay = frw)
                float w5b = 0.0f, rhsb = 0.0f, rhsb0 = 0.0f;
                if constexpr (P >= 2) {
                    w5b = 5.0f * fmaxf(fminf(x1, bx1b) - fmaxf(x0, bx0b) + 1.0f, 0.0f);
                    rhsb  = fmaf(ax, frw1, saB);
                    rhsb0 = fmaf(ax, frw,  saB);
                }

                int a = xi * SATP + (c << 2);   // 16B-aligned
                float4 TL = *(const float4*)(S + a);
                float4 BL = *(const float4*)(S + a + R_);
                const float* hp0 = HYS + cYQ(r) + (c << 2);
                int off = base + xi * nc + (c << 2);

                #pragma unroll 1
                for (int q = c; q < nq; q += qstep) {
                    float4 TR = *(const float4*)(S + a + rw);
                    float4 BR = *(const float4*)(S + a + R_ + rw);
                    // EXACT scoring expression/order (bit-identical)
                    float s0 = (BR.x - TR.x - BL.x + TL.x) * inv;
                    float s1 = (BR.y - TR.y - BL.y + TL.y) * inv;
                    float s2 = (BR.z - TR.z - BL.z + TL.z) * inv;
                    float s3 = (BR.w - TR.w - BL.w + TL.w) * inv;
                    float4 h4 = *(const float4*)hp0;
                    bool k0 = (w5a * h4.x <= ((q == 0) ? rhsa0 : rhsa));
                    bool k1 = (w5a * h4.y <= rhsa);
                    bool k2 = (w5a * h4.z <= rhsa);
                    bool k3 = (w5a * h4.w <= rhsa);
                    if constexpr (P >= 2) {
                        float4 g4 = *(const float4*)(hp0 + NYS);
                        k0 &= (w5b * g4.x <= ((q == 0) ? rhsb0 : rhsb));
                        k1 &= (w5b * g4.y <= rhsb);
                        k2 &= (w5b * g4.z <= rhsb);
                        k3 &= (w5b * g4.w <= rhsb);
                    }
                    bool full = (q != nq - 1);
                    // strict '>' — per-thread ascending order keeps min index
                    if (k0 &&         s0 > best) { best = s0; bidx = off;     }
                    if (k1 && full && s1 > best) { best = s1; bidx = off + 1; }
                    if (k2 && full && s2 > best) { best = s2; bidx = off + 2; }
                    if (k3 && full && s3 > best) { best = s3; bidx = off + 3; }
                    TL = TR; BL = BR;
                    a += rw; off += rw; hp0 += rw;
                }
            }
        }
    }
}

__global__ void __launch_bounds__(NTH, 2)
appm_kernel(const float* __restrict__ x, float* __restrict__ out)
{
    extern __shared__ float SH[];
    float* S   = SH;                    // SATN * SATP padded SAT
    float* HYS = SH + SATN * SATP;      // 2 slots * NYS

    __shared__ float red_s[3][32];
    __shared__ int   red_i[3][32];
    __shared__ float boxsm[4][4];       // pick0 g0/g1/g2, g1-pick1
    __shared__ float sarea[4];
    __shared__ float TOT[452];          // segment totals for 2-level prefixes

    const int tid  = threadIdx.x;
    const int b    = blockIdx.x;
    const int lane = tid & 31;
    const int warp = tid >> 5;

    const float* __restrict__ xb = x + (size_t)b * (FEAT * FEAT);

    // ---- (1) SAT build (padded stride 116; cols 113-115 stay zero) --------
    for (int k = tid; k < SATN * SATP; k += NTH) {
        int i = k / SATP;
        int j = k - i * SATP;
        float v = 0.0f;
        if (i > 0 && j > 0 && j < SATN) v = xb[(i - 1) * FEAT + (j - 1)];
        S[k] = v;
    }
    __syncthreads();

    // row prefix, 2-level: 113 rows x 4 segments of 28 cols (cols 1..112)
    if (tid < 452) {
        int r = tid >> 2, s = tid & 3;
        float* row = S + r * SATP;
        int j0 = 1 + s * 28;
        float acc = 0.0f;
        #pragma unroll
        for (int j = 0; j < 28; j++) { acc += row[j0 + j]; row[j0 + j] = acc; }
        TOT[tid] = acc;
    }
    __syncthreads();
    if (tid < 452) {
        int r = tid >> 2, s = tid & 3;
        if (s > 0) {
            float carry = TOT[(r << 2)];
            if (s > 1) carry += TOT[(r << 2) + 1];
            if (s > 2) carry += TOT[(r << 2) + 2];
            float* row = S + r * SATP;
            int j0 = 1 + s * 28;
            #pragma unroll
            for (int j = 0; j < 28; j++) row[j0 + j] += carry;
        }
    }
    __syncthreads();

    // column prefix, 2-level: 113 cols x 4 segments of 28 rows (rows 1..112)
    if (tid < 452) {
        int c = tid >> 2, s = tid & 3;
        int i0 = 1 + s * 28;
        float acc = 0.0f;
        #pragma unroll
        for (int i = 0; i < 28; i++) {
            acc += S[(i0 + i) * SATP + c];
            S[(i0 + i) * SATP + c] = acc;
        }
        TOT[tid] = acc;
    }
    __syncthreads();
    if (tid < 452) {
        int c = tid >> 2, s = tid & 3;
        if (s > 0) {
            float carry = TOT[(c << 2)];
            if (s > 1) carry += TOT[(c << 2) + 1];
            if (s > 2) carry += TOT[(c << 2) + 2];
            int i0 = 1 + s * 28;
            #pragma unroll
            for (int i = 0; i < 28; i++) S[(i0 + i) * SATP + c] += carry;
        }
    }
    __syncthreads();

    // ---- (2) window scores -> gmem via float4 SAT tiles, fused pick0 ------
    float* ws = out + 2 * (NBATCH * PROPN) + (size_t)b * NTOTAL;

    float bst[3] = {NEGINF, NEGINF, NEGINF};
    int   bix[3] = {0x7fffffff, 0x7fffffff, 0x7fffffff};

    #pragma unroll
    for (int r = 0; r < NRAT; r++) {
        const int rh = cRH(r), rw = cRW(r);
        const int nr = SATN - rh, nc = SATN - rw;
        const int nq = (nc + 3) >> 2;
        const int ntile = nr * nq;
        const float inv = 1.0f / (float)(rh * rw);
        const int base = cBASE(r);
        const int g = (r < 3) ? 0 : (r < 6) ? 1 : 2;
        const int R_ = rh * SATP;
        float* wsr = ws + base;
        #pragma unroll 1
        for (int t = tid; t < ntile; t += NTH) {
            int xi = t / nq;
            int q  = t - xi * nq;
            int yi = q << 2;
            int a  = xi * SATP + yi;    // 16B-aligned
            float4 v0 = *(const float4*)(S + a);
            float4 v1 = *(const float4*)(S + a + rw);
            float4 v2 = *(const float4*)(S + a + R_);
            float4 v3 = *(const float4*)(S + a + R_ + rw);
            float s0 = (v3.x - v1.x - v2.x + v0.x) * inv;
            float s1 = (v3.y - v1.y - v2.y + v0.y) * inv;
            float s2 = (v3.z - v1.z - v2.z + v0.z) * inv;
            float s3 = (v3.w - v1.w - v2.w + v0.w) * inv;
            int off = xi * nc + yi;
            if (q != nq - 1) {
                wsr[off]     = s0;
                wsr[off + 1] = s1;
                wsr[off + 2] = s2;
                wsr[off + 3] = s3;
                if (s0 > bst[g]) { bst[g] = s0; bix[g] = base + off; }
                if (s1 > bst[g]) { bst[g] = s1; bix[g] = base + off + 1; }
                if (s2 > bst[g]) { bst[g] = s2; bix[g] = base + off + 2; }
                if (s3 > bst[g]) { bst[g] = s3; bix[g] = base + off + 3; }
            } else {
                wsr[off] = s0;
                if (s0 > bst[g]) { bst[g] = s0; bix[g] = base + off; }
            }
        }
    }

    // ---- (3a) batched 3-way reduction: pick0 of each group ----------------
    {
        #pragma unroll
        for (int g = 0; g < 3; g++) wmerge(bst[g], bix[g]);
        if (lane == 0)
            #pragma unroll
            for (int g = 0; g < 3; g++) { red_s[g][warp] = bst[g]; red_i[g][warp] = bix[g]; }
        __syncthreads();
        if (warp == 0) {
            float bb[3]; int ii[3];
            #pragma unroll
            for (int g = 0; g < 3; g++) { bb[g] = red_s[g][lane]; ii[g] = red_i[g][lane]; wmerge(bb[g], ii[g]); }
            if (lane == 0) {
                const int slot[3] = {0, 2, 5};
                #pragma unroll
                for (int g = 0; g < 3; g++) {
                    out[b * PROPN + slot[g]] = (float)ii[g];
                    out[NBATCH * PROPN + b * PROPN + slot[g]] = bb[g];
                    decode_box(ii[g], boxsm[g], &sarea[g]);
                }
            }
        }
        __syncthreads();
    }

    // ---- (3b) hy tables (slot 0) for all 3 groups' pick0 priors ------------
    fill_hys<0, 3>(0, tid, HYS, boxsm[0]);
    fill_hys<3, 6>(0, tid, HYS, boxsm[1]);
    fill_hys<6, 13>(0, tid, HYS, boxsm[2]);
    __syncthreads();

    // ---- (3c) pick1 scans (rolling y-chains, no gmem) -----------------------
    float b0x0 = boxsm[0][0], b0x1 = boxsm[0][2];
    float b1x0 = boxsm[1][0], b1x1 = boxsm[1][2];
    float b2x0 = boxsm[2][0], b2x1 = boxsm[2][2];
    float sa0 = sarea[0], sa1g = sarea[1], sa2 = sarea[2];

    bst[0] = bst[1] = bst[2] = NEGINF;
    bix[0] = bix[1] = bix[2] = 0x7fffffff;
    nms_scan<0, 3, 1>(S, HYS, b0x0, b0x1, sa0,  0, 0, 0, tid, bst[0], bix[0]);
    nms_scan<3, 6, 1>(S, HYS, b1x0, b1x1, sa1g, 0, 0, 0, tid, bst[1], bix[1]);
    nms_scan<6, 13, 1>(S, HYS, b2x0, b2x1, sa2, 0, 0, 0, tid, bst[2], bix[2]);

    // ---- (3d) batched reduction: pick1s; decode only g1's winner -----------
    {
        #pragma unroll
        for (int g = 0; g < 3; g++) wmerge(bst[g], bix[g]);
        if (lane == 0)
            #pragma unroll
            for (int g = 0; g < 3; g++) { red_s[g][warp] = bst[g]; red_i[g][warp] = bix[g]; }
        __syncthreads();
        if (warp == 0) {
            float bb[3]; int ii[3];
            #pragma unroll
            for (int g = 0; g < 3; g++) { bb[g] = red_s[g][lane]; ii[g] = red_i[g][lane]; wmerge(bb[g], ii[g]); }
            if (lane == 0) {
                const int slot[3] = {1, 3, 6};
                #pragma unroll
                for (int g = 0; g < 3; g++) {
                    out[b * PROPN + slot[g]] = (float)ii[g];
                    out[NBATCH * PROPN + b * PROPN + slot[g]] = bb[g];
                }
                decode_box(ii[1], boxsm[3], &sarea[3]);
            }
        }
        __syncthreads();
    }

    // ---- (3e) g1 pick2: slot-1 tables, 2-prior chain scan -------------------
    fill_hys<3, 6>(1, tid, HYS, boxsm[3]);
    __syncthreads();
    float b3x0 = boxsm[3][0], b3x1 = boxsm[3][2];
    float nb = NEGINF; int ni = 0x7fffffff;
    nms_scan<3, 6, 2>(S, HYS, b1x0, b1x1, sa1g,
                      b3x0, b3x1, sarea[3], tid, nb, ni);
    {
        wmerge(nb, ni);
        if (lane == 0) { red_s[0][warp] = nb; red_i[0][warp] = ni; }
        __syncthreads();
        if (warp == 0) {
            nb = red_s[0][lane]; ni = red_i[0][lane];
            wmerge(nb, ni);
            if (lane == 0) {
                out[b * PROPN + 4] = (float)ni;
                out[NBATCH * PROPN + b * PROPN + 4] = nb;
            }
        }
    }
}

extern "C" void kernel_launch(void* const* d_in, const int* in_sizes, int n_in,
                              void* d_out, int out_size) {
    const float* x = (const float*)d_in[0];
    float* out = (float*)d_out;
    (void)in_sizes; (void)n_in; (void)out_size;

    const int smem = SMEM_FLOATS * (int)sizeof(float);  // 61712 B
    cudaFuncSetAttribute(appm_kernel, cudaFuncAttributeMaxDynamicSharedMemorySize, smem);
    appm_kernel<<<NBATCH, NTH, smem>>>(x, out);
}